// round 9
// baseline (speedup 1.0000x reference)
#include <cuda_runtime.h>
#include <math.h>
#include <stdint.h>

// Problem constants
#define BB     32
#define LL     4096
#define DIN    150
#define DST    75
#define HID    75
#define HIDP   80
#define K2N    75           // DIN/2 k-pairs
#define TILE_L 64
#define NCHUNK (LL / TILE_L)     // 64
#define WORKS  (BB * NCHUNK)     // 2048
#define GRIDC  296               // 2 persistent CTAs per SM
#define NTH    256
#define XT_STR 66            // xs_t row stride in float2 units (even -> 16B align)

typedef unsigned long long ull;

// cross-CTA reduction scratch
__device__ float g_part[BB][NCHUNK][160];
__device__ float g_psum[BB][NCHUNK];
__device__ int   g_done_b[BB];      // zero-init; reset by finisher each pass

__device__ __forceinline__ void ffma2(ull& d, ull a, ull b) {
    asm("fma.rn.f32x2 %0, %1, %2, %0;" : "+l"(d) : "l"(a), "l"(b));
}
__device__ __forceinline__ float tanh_approx(float x) {
    float t;
    asm("tanh.approx.f32 %0, %1;" : "=f"(t) : "f"(x));
    return t;
}

// ---------------------------------------------------------------------------
// Persistent fused kernel, 2 CTAs/SM (4 warps/SMSP). Tile = 64 rows.
// Thread tile: 4 rows x 5 col-pairs. xv = 2 x LDS.128, wv = 5 x LDS.64.
// ---------------------------------------------------------------------------
__global__ __launch_bounds__(NTH, 2)
void k_fused(const float* __restrict__ inputs,
             const float* __restrict__ state,
             const int*   __restrict__ cmask,
             const float* __restrict__ W0,
             const float* __restrict__ b0,
             const float* __restrict__ W1,
             const float* __restrict__ b1,
             float* __restrict__ res,
             float* __restrict__ s1_out) {
    extern __shared__ float sm[];
    float* xs_t    = sm;                              // [K2N][XT_STR] float2
    float2* ws2    = (float2*)(sm + K2N * XT_STR * 2);     // [K2N][HIDP]
    float* spb_all = sm + K2N * XT_STR * 2 + K2N * HIDP * 2;  // [BB][HIDP]
    float* w1s     = spb_all + BB * HIDP;             // [HIDP]
    float* es      = w1s + HIDP;                      // [TILE_L]
    float* psred   = es + TILE_L;                     // [2]
    __shared__ int s_flag;

    const int tid = threadIdx.x;
    const int cta = blockIdx.x;

    // --- stage W0 input-part repacked as k-pairs (once per CTA) ---
    for (int idx = tid; idx < K2N * HIDP; idx += NTH) {
        int k2 = idx / HIDP;
        int j  = idx - k2 * HIDP;
        float2 w;
        if (j < HID) {
            w.x = W0[(DST + 2 * k2)     * HID + j];
            w.y = W0[(DST + 2 * k2 + 1) * HID + j];
        } else { w.x = 0.0f; w.y = 0.0f; }
        ws2[idx] = w;
    }
    // --- state projections for all batches (once per CTA) ---
    for (int idx = tid; idx < BB * HIDP; idx += NTH) {
        int b = idx / HIDP;
        int j = idx - b * HIDP;
        float acc = 0.0f;
        if (j < HID) {
            acc = b0[j];
            const float* st = state + b * DST;
#pragma unroll 15
            for (int k = 0; k < DST; ++k)
                acc = fmaf(st[k], W0[k * HID + j], acc);
        }
        spb_all[idx] = acc;
    }
    if (tid < HIDP)
        w1s[tid] = (tid < HID) ? W1[tid] : 0.0f;
    __syncthreads();

    const int tx = tid & 15;          // col group: cols tx*5 .. tx*5+4
    const int ty = tid >> 4;          // row group: rows ty*4 .. ty*4+3
    const int r0 = ty * 4;
    const float b1v = b1[0];

    float w1c[5];
#pragma unroll
    for (int c = 0; c < 5; ++c) w1c[c] = w1s[tx * 5 + c];

    // ---------------- persistent work loop ----------------
    for (int w = cta; w < WORKS; w += GRIDC) {
        const int b     = w >> 6;
        const int chunk = w & (NCHUNK - 1);
        const int l0    = chunk * TILE_L;

        // --- stage transposed x tile: xs_t[k2][r] = (x[r][2k2], x[r][2k2+1])
        {
            const float2* gin = (const float2*)(inputs + ((size_t)b * LL + l0) * DIN);
            float2* xt2 = (float2*)xs_t;
            for (int idx = tid; idx < K2N * TILE_L; idx += NTH) {
                int r  = idx & (TILE_L - 1);
                int k2 = idx >> 6;
                xt2[k2 * XT_STR + r] = gin[(size_t)r * K2N + k2];
            }
        }
        __syncthreads();

        // ---- GEMM: 4 rows x 5 col-pairs, FFMA2 over 75 k-pairs
        ull acc[4][5];
#pragma unroll
        for (int i = 0; i < 4; ++i)
#pragma unroll
            for (int c = 0; c < 5; ++c) acc[i][c] = 0ULL;

        const ull* xbase = (const ull*)xs_t + r0;         // + k2*XT_STR (even)
        const ull* wbase = (const ull*)ws2 + tx * 5;      // + k2*HIDP

#pragma unroll 5
        for (int k2 = 0; k2 < K2N; ++k2) {
            const ull* xr = xbase + (size_t)k2 * XT_STR;
            ulonglong2 xv01 = *(const ulonglong2*)(xr);
            ulonglong2 xv23 = *(const ulonglong2*)(xr + 2);
            ull xv[4] = { xv01.x, xv01.y, xv23.x, xv23.y };
            const ull* wr = wbase + (size_t)k2 * HIDP;
            ull wv[5] = { wr[0], wr[1], wr[2], wr[3], wr[4] };
#pragma unroll
            for (int i = 0; i < 4; ++i)
#pragma unroll
                for (int c = 0; c < 5; ++c)
                    ffma2(acc[i][c], xv[i], wv[c]);
        }

        // ---- epilogue: tanh + dot(W1) + 16-lane reduce + mask + exp
        float spc[5];
#pragma unroll
        for (int c = 0; c < 5; ++c) spc[c] = spb_all[b * HIDP + tx * 5 + c];

#pragma unroll
        for (int i = 0; i < 4; ++i) {
            float s = 0.0f;
#pragma unroll
            for (int c = 0; c < 5; ++c) {
                ull a = acc[i][c];
                float lo = __uint_as_float((unsigned)(a & 0xffffffffu));
                float hi = __uint_as_float((unsigned)(a >> 32));
                float h  = lo + hi + spc[c];
                s = fmaf(tanh_approx(h), w1c[c], s);
            }
            s += __shfl_xor_sync(0xffffffffu, s, 1);
            s += __shfl_xor_sync(0xffffffffu, s, 2);
            s += __shfl_xor_sync(0xffffffffu, s, 4);
            s += __shfl_xor_sync(0xffffffffu, s, 8);
            if (tx == 0) {
                int r = r0 + i;
                size_t idx = (size_t)b * LL + l0 + r;
                float sv = s + b1v;
                if (cmask[idx] == 0) sv -= 1e30f;
                s1_out[idx] = sv;
                es[r] = __expf(sv);    // masked -> 0
            }
        }
        __syncthreads();

        // ---- fused weighted partial sums from resident transposed tile
        if (tid < DIN) {
            const int f2   = tid >> 1;
            const int comp = tid & 1;
            const float* xcol = xs_t + (size_t)f2 * (XT_STR * 2) + comp;
            float p = 0.0f;
#pragma unroll 8
            for (int r = 0; r < TILE_L; ++r)
                p = fmaf(es[r], xcol[2 * r], p);
            g_part[b][chunk][tid] = p;
        }
        if (tid < TILE_L) {   // 2 warps reduce 64 exp values
            float v = es[tid];
            v += __shfl_xor_sync(0xffffffffu, v, 16);
            v += __shfl_xor_sync(0xffffffffu, v, 8);
            v += __shfl_xor_sync(0xffffffffu, v, 4);
            v += __shfl_xor_sync(0xffffffffu, v, 2);
            v += __shfl_xor_sync(0xffffffffu, v, 1);
            if ((tid & 31) == 0) psred[tid >> 5] = v;
        }
        __syncthreads();
        if (tid == 0) {
            g_psum[b][chunk] = psred[0] + psred[1];
            __threadfence();
            int old = atomicAdd(&g_done_b[b], 1);
            s_flag = (old == NCHUNK - 1);
        }
        __syncthreads();

        // ---- last CTA to finish batch b computes res[b]
        if (s_flag) {
            __threadfence();
            if (tid < DIN) {
                float tot = 0.0f;
#pragma unroll
                for (int c = 0; c < NCHUNK; ++c) tot += g_psum[b][c];
                float p = 0.0f;
#pragma unroll
                for (int c = 0; c < NCHUNK; ++c) p += g_part[b][c][tid];
                res[b * DIN + tid] = p / tot;
            }
            if (tid == 0) g_done_b[b] = 0;   // reset for next replay
        }
        __syncthreads();
    }
}

// ---------------------------------------------------------------------------
extern "C" void kernel_launch(void* const* d_in, const int* in_sizes, int n_in,
                              void* d_out, int out_size) {
    const float* inputs = (const float*)d_in[0];
    const float* state  = (const float*)d_in[1];
    const int*   cmask  = (const int*)d_in[2];   // bool transported as int32
    const float* W0     = (const float*)d_in[3];
    const float* b0     = (const float*)d_in[4];
    const float* W1     = (const float*)d_in[5];
    const float* b1     = (const float*)d_in[6];

    float* out = (float*)d_out;
    float* res = out;                 // [B][1][DIN] = 4800 floats
    float* s1  = out + BB * DIN;      // [B][L]      = 131072 floats

    const int smem = (K2N * XT_STR * 2 + K2N * HIDP * 2 + BB * HIDP + HIDP
                      + TILE_L + 2) * (int)sizeof(float);
    cudaFuncSetAttribute(k_fused, cudaFuncAttributeMaxDynamicSharedMemorySize, smem);

    k_fused<<<GRIDC, NTH, smem>>>(inputs, state, cmask, W0, b0, W1, b1, res, s1);
}

// round 10
// speedup vs baseline: 1.1406x; 1.1406x over previous
#include <cuda_runtime.h>
#include <math.h>
#include <stdint.h>

// Problem constants
#define BB     32
#define LL     4096
#define DIN    150
#define DST    75
#define HID    75
#define HIDP   80
#define K2N    75          // DIN/2 k-pairs
#define TILE_L 128
#define NCHUNK (LL / TILE_L)     // 32
#define WORKS  (BB * NCHUNK)     // 1024
#define GRIDC  148
#define NTH    256
#define TFLOATS (TILE_L * DIN)   // 19200 floats per x tile (flat row-major)
#define CHUNK16 (TFLOATS * 4 / 16)  // 4800 16B chunks per tile

typedef unsigned long long ull;

// cross-CTA reduction scratch
__device__ float g_part[BB][NCHUNK][160];
__device__ float g_psum[BB][NCHUNK];
__device__ int   g_done_b[BB];      // zero-init; reset by finisher each launch

__device__ __forceinline__ void ffma2(ull& d, ull a, ull b) {
    asm("fma.rn.f32x2 %0, %1, %2, %0;" : "+l"(d) : "l"(a), "l"(b));
}
__device__ __forceinline__ float tanh_approx(float x) {
    float t;
    asm("tanh.approx.f32 %0, %1;" : "=f"(t) : "f"(x));
    return t;
}
__device__ __forceinline__ void cp16(uint32_t saddr, const void* gptr) {
    asm volatile("cp.async.cg.shared.global [%0], [%1], 16;"
                 :: "r"(saddr), "l"(gptr));
}
__device__ __forceinline__ void cp_commit() {
    asm volatile("cp.async.commit_group;");
}
__device__ __forceinline__ void cp_wait1() {
    asm volatile("cp.async.wait_group 1;");
}
__device__ __forceinline__ void cp_wait0() {
    asm volatile("cp.async.wait_group 0;");
}

// ---------------------------------------------------------------------------
// Persistent fused kernel (R8 structure) with SOFTWARE-PIPELINED inner loop:
// loads for k2+1 are issued before the FMA block of k2, hiding LDS latency.
// ---------------------------------------------------------------------------
__global__ __launch_bounds__(NTH, 1)
void k_fused(const float* __restrict__ inputs,
             const float* __restrict__ state,
             const int*   __restrict__ cmask,
             const float* __restrict__ W0,
             const float* __restrict__ b0,
             const float* __restrict__ W1,
             const float* __restrict__ b1,
             float* __restrict__ res,
             float* __restrict__ s1_out) {
    extern __shared__ float sm[];
    float* xs0     = sm;                       // [19200] tile buf 0 (flat)
    float* xs1     = sm + TFLOATS;             // [19200] tile buf 1
    float2* ws2    = (float2*)(sm + 2 * TFLOATS);   // [K2N][HIDP] k-pairs
    float* spb_all = sm + 2 * TFLOATS + K2N * HIDP * 2 + 16;  // [BB][HIDP] (+16 pad for k2 overread)
    float* w1s     = spb_all + BB * HIDP;      // [HIDP]
    float* es      = w1s + HIDP;               // [TILE_L]
    float* psred   = es + TILE_L;              // [4]
    __shared__ int s_flag;

    const int tid = threadIdx.x;
    const int cta = blockIdx.x;
    const int nw  = (WORKS - cta + GRIDC - 1) / GRIDC;   // my work count

    // --- prefetch first tile into buf0 ---
    {
        int w0i = cta;
        int b = w0i >> 5, chunk = w0i & 31;
        const char* gbase = (const char*)(inputs + ((size_t)b * LL + chunk * TILE_L) * DIN);
        uint32_t sbase = (uint32_t)__cvta_generic_to_shared(xs0);
        for (int c = tid; c < CHUNK16; c += NTH)
            cp16(sbase + c * 16, gbase + (size_t)c * 16);
        cp_commit();
    }

    // --- stage W0 input-part repacked as k-pairs (once) ---
    for (int idx = tid; idx < K2N * HIDP; idx += NTH) {
        int k2 = idx / HIDP;
        int j  = idx - k2 * HIDP;
        float2 w;
        if (j < HID) {
            w.x = W0[(DST + 2 * k2)     * HID + j];
            w.y = W0[(DST + 2 * k2 + 1) * HID + j];
        } else { w.x = 0.0f; w.y = 0.0f; }
        ws2[idx] = w;
    }
    // --- state projections for all batches (once) ---
    for (int idx = tid; idx < BB * HIDP; idx += NTH) {
        int b = idx / HIDP;
        int j = idx - b * HIDP;
        float acc = 0.0f;
        if (j < HID) {
            acc = b0[j];
            const float* st = state + b * DST;
#pragma unroll 15
            for (int k = 0; k < DST; ++k)
                acc = fmaf(st[k], W0[k * HID + j], acc);
        }
        spb_all[idx] = acc;
    }
    if (tid < HIDP)
        w1s[tid] = (tid < HID) ? W1[tid] : 0.0f;

    const int tx = tid & 15;          // col group: cols tx*5 .. tx*5+4
    const int ty = tid >> 4;          // row group: rows ty*8 .. ty*8+7
    const int r0 = ty * 8;
    const float b1v = b1[0];

    float w1c[5];
#pragma unroll
    for (int c = 0; c < 5; ++c) w1c[c] = 0.0f;   // loaded after first sync

    // ---------------- persistent work loop ----------------
    for (int wi = 0; wi < nw; ++wi) {
        const int w     = cta + wi * GRIDC;
        const int b     = w >> 5;
        const int chunk = w & 31;
        const int l0    = chunk * TILE_L;
        float* xsb = (wi & 1) ? xs1 : xs0;

        // prefetch next tile into the other buffer
        if (wi + 1 < nw) {
            int w2 = cta + (wi + 1) * GRIDC;
            int b2 = w2 >> 5, ch2 = w2 & 31;
            const char* gbase = (const char*)(inputs + ((size_t)b2 * LL + ch2 * TILE_L) * DIN);
            float* dst = ((wi + 1) & 1) ? xs1 : xs0;
            uint32_t sbase = (uint32_t)__cvta_generic_to_shared(dst);
            for (int c = tid; c < CHUNK16; c += NTH)
                cp16(sbase + c * 16, gbase + (size_t)c * 16);
            cp_commit();
            cp_wait1();              // current buffer's group complete
        } else {
            cp_wait0();
        }
        __syncthreads();             // staging (wi==0: also ws2/spb) visible

        if (wi == 0) {
#pragma unroll
            for (int c = 0; c < 5; ++c) w1c[c] = w1s[tx * 5 + c];
        }

        // ---- GEMM: 8 rows x 5 col-pairs per thread, software-pipelined
        ull acc[8][5];
#pragma unroll
        for (int i = 0; i < 8; ++i)
#pragma unroll
            for (int c = 0; c < 5; ++c) acc[i][c] = 0ULL;

        const ull* xb = (const ull*)xsb + (size_t)r0 * K2N;   // row-major, 75 ull/row
        const ull* wbase = (const ull*)ws2 + tx * 5;

        ull xv[8], wv[5];
#pragma unroll
        for (int i = 0; i < 8; ++i) xv[i] = xb[(size_t)i * K2N];
#pragma unroll
        for (int c = 0; c < 5; ++c) wv[c] = wbase[c];

#pragma unroll 5
        for (int k2 = 0; k2 < K2N; ++k2) {
            // prefetch k2+1 (one-past-end read stays inside dyn smem; unused)
            ull xn[8], wn[5];
#pragma unroll
            for (int i = 0; i < 8; ++i)
                xn[i] = xb[(size_t)i * K2N + k2 + 1];
            const ull* wr = wbase + (size_t)(k2 + 1) * HIDP;
#pragma unroll
            for (int c = 0; c < 5; ++c) wn[c] = wr[c];
            // FMAs for k2
#pragma unroll
            for (int i = 0; i < 8; ++i)
#pragma unroll
                for (int c = 0; c < 5; ++c)
                    ffma2(acc[i][c], xv[i], wv[c]);
            // rotate
#pragma unroll
            for (int i = 0; i < 8; ++i) xv[i] = xn[i];
#pragma unroll
            for (int c = 0; c < 5; ++c) wv[c] = wn[c];
        }

        // ---- epilogue: tanh + dot(W1) + 16-lane reduce + mask + exp
        float spc[5];
#pragma unroll
        for (int c = 0; c < 5; ++c) spc[c] = spb_all[b * HIDP + tx * 5 + c];

#pragma unroll
        for (int i = 0; i < 8; ++i) {
            float s = 0.0f;
#pragma unroll
            for (int c = 0; c < 5; ++c) {
                ull a = acc[i][c];
                float lo = __uint_as_float((unsigned)(a & 0xffffffffu));
                float hi = __uint_as_float((unsigned)(a >> 32));
                float h  = lo + hi + spc[c];
                s = fmaf(tanh_approx(h), w1c[c], s);
            }
            s += __shfl_xor_sync(0xffffffffu, s, 1);
            s += __shfl_xor_sync(0xffffffffu, s, 2);
            s += __shfl_xor_sync(0xffffffffu, s, 4);
            s += __shfl_xor_sync(0xffffffffu, s, 8);
            if (tx == 0) {
                int r = r0 + i;
                size_t idx = (size_t)b * LL + l0 + r;
                float sv = s + b1v;
                if (cmask[idx] == 0) sv -= 1e30f;
                s1_out[idx] = sv;
                es[r] = __expf(sv);    // masked -> 0
            }
        }
        __syncthreads();

        // ---- fused weighted partial sums from resident tile
        if (tid < DIN) {
            const float* xcol = xsb + tid;
            float p = 0.0f;
#pragma unroll 8
            for (int r = 0; r < TILE_L; ++r)
                p = fmaf(es[r], xcol[(size_t)r * DIN], p);
            g_part[b][chunk][tid] = p;
        }
        if (tid < TILE_L) {
            float v = es[tid];
            v += __shfl_xor_sync(0xffffffffu, v, 16);
            v += __shfl_xor_sync(0xffffffffu, v, 8);
            v += __shfl_xor_sync(0xffffffffu, v, 4);
            v += __shfl_xor_sync(0xffffffffu, v, 2);
            v += __shfl_xor_sync(0xffffffffu, v, 1);
            if ((tid & 31) == 0) psred[tid >> 5] = v;
        }
        __syncthreads();
        if (tid == 0) {
            g_psum[b][chunk] = (psred[0] + psred[1]) + (psred[2] + psred[3]);
            __threadfence();
            int old = atomicAdd(&g_done_b[b], 1);
            s_flag = (old == NCHUNK - 1);
        }
        __syncthreads();

        // ---- last CTA to finish batch b computes res[b]
        if (s_flag) {
            __threadfence();
            if (tid < DIN) {
                float tot = 0.0f;
#pragma unroll
                for (int c = 0; c < NCHUNK; ++c) tot += g_psum[b][c];
                float p = 0.0f;
#pragma unroll
                for (int c = 0; c < NCHUNK; ++c) p += g_part[b][c][tid];
                res[b * DIN + tid] = p / tot;
            }
            if (tid == 0) g_done_b[b] = 0;   // reset for next launch/replay
        }
        __syncthreads();
    }
}

// ---------------------------------------------------------------------------
extern "C" void kernel_launch(void* const* d_in, const int* in_sizes, int n_in,
                              void* d_out, int out_size) {
    const float* inputs = (const float*)d_in[0];
    const float* state  = (const float*)d_in[1];
    const int*   cmask  = (const int*)d_in[2];   // bool transported as int32
    const float* W0     = (const float*)d_in[3];
    const float* b0     = (const float*)d_in[4];
    const float* W1     = (const float*)d_in[5];
    const float* b1     = (const float*)d_in[6];

    float* out = (float*)d_out;
    float* res = out;                 // [B][1][DIN] = 4800 floats
    float* s1  = out + BB * DIN;      // [B][L]      = 131072 floats

    const int smem = (2 * TFLOATS + K2N * HIDP * 2 + 16 + BB * HIDP + HIDP
                      + TILE_L + 4) * (int)sizeof(float);
    cudaFuncSetAttribute(k_fused, cudaFuncAttributeMaxDynamicSharedMemorySize, smem);

    k_fused<<<GRIDC, NTH, smem>>>(inputs, state, cmask, W0, b0, W1, b1, res, s1);
}

// round 12
// speedup vs baseline: 1.5881x; 1.3923x over previous
#include <cuda_runtime.h>
#include <cuda_bf16.h>
#include <math.h>
#include <stdint.h>

#define BB     32
#define LL     4096
#define DIN    150
#define DST    75
#define HID    75
#define HIDP   80
#define TILE_L 128
#define NCHUNK (LL / TILE_L)     // 32
#define WORKS  (BB * NCHUNK)     // 1024
#define GRIDC  148
#define NTH    256
#define TFLOATS (TILE_L * DIN)   // 19200
#define CHUNK16 (TFLOATS * 4 / 16)
#define WKS    168               // W row stride in bf16 (21*16B -> conflict-free LDSM)
#define WROWB  (WKS * 2)         // 336 bytes
#define WFLOATS (HIDP * WKS / 2) // 6720 floats per matrix

// smem float offsets
#define OFF_XS0 0
#define OFF_XS1 19200
#define OFF_WH  38400
#define OFF_WL  (OFF_WH + WFLOATS)
#define OFF_SPB (OFF_WL + WFLOATS)
#define OFF_W1  (OFF_SPB + BB * HIDP)
#define OFF_ES  (OFF_W1 + HIDP)
#define OFF_PS  (OFF_ES + TILE_L)
#define SMEM_FLOATS (OFF_PS + 8)

__device__ float g_part[BB][NCHUNK][160];
__device__ float g_psum[BB][NCHUNK];
__device__ int   g_done_b[BB];

__device__ __forceinline__ float tanh_approx(float x) {
    float t; asm("tanh.approx.f32 %0, %1;" : "=f"(t) : "f"(x)); return t;
}
__device__ __forceinline__ void cp16(uint32_t saddr, const void* gptr) {
    asm volatile("cp.async.cg.shared.global [%0], [%1], 16;" :: "r"(saddr), "l"(gptr));
}
__device__ __forceinline__ void cp_commit() { asm volatile("cp.async.commit_group;"); }
__device__ __forceinline__ void cp_wait1()  { asm volatile("cp.async.wait_group 1;"); }
__device__ __forceinline__ void cp_wait0()  { asm volatile("cp.async.wait_group 0;"); }
__device__ __forceinline__ uint32_t smem_u32(const void* p) {
    uint32_t a;
    asm("{ .reg .u64 t; cvta.to.shared.u64 t, %1; cvt.u32.u64 %0, t; }" : "=r"(a) : "l"(p));
    return a;
}
// pack (f.x -> low half, f.y -> high half) as bf16x2, round-to-nearest
__device__ __forceinline__ uint32_t bfpack(float2 f) {
    uint32_t r;
    asm("cvt.rn.bf16x2.f32 %0, %1, %2;" : "=r"(r) : "f"(f.y), "f"(f.x));
    return r;
}
// residual pair: f - bf16(f), packed bf16x2
__device__ __forceinline__ uint32_t bfres(float2 f, uint32_t h) {
    float hx = __uint_as_float(h << 16);
    float hy = __uint_as_float(h & 0xffff0000u);
    float2 r; r.x = f.x - hx; r.y = f.y - hy;
    return bfpack(r);
}

#define LDSM_X2(r0, r1, addr) \
    asm volatile("ldmatrix.sync.aligned.m8n8.x2.shared.b16 {%0,%1}, [%2];" \
                 : "=r"(r0), "=r"(r1) : "r"(addr))

#define MMA_BF16(d, a0, a1, a2, a3, b0, b1) \
    asm volatile("mma.sync.aligned.m16n8k16.row.col.f32.bf16.bf16.f32 " \
                 "{%0,%1,%2,%3}, {%4,%5,%6,%7}, {%8,%9}, {%0,%1,%2,%3};" \
                 : "+f"((d)[0]), "+f"((d)[1]), "+f"((d)[2]), "+f"((d)[3]) \
                 : "r"(a0), "r"(a1), "r"(a2), "r"(a3), "r"(b0), "r"(b1))

// ---------------------------------------------------------------------------
// Persistent fused kernel: bf16 mma.sync (3xBF16) scores GEMM + tanh/dot +
// mask + exp + fused weighted partials + per-batch finish.
// ---------------------------------------------------------------------------
__global__ __launch_bounds__(NTH, 1)
void k_fused(const float* __restrict__ inputs,
             const float* __restrict__ state,
             const int*   __restrict__ cmask,
             const float* __restrict__ W0,
             const float* __restrict__ b0,
             const float* __restrict__ W1,
             const float* __restrict__ b1,
             float* __restrict__ res,
             float* __restrict__ s1_out) {
    extern __shared__ float sm[];
    float* xs0     = sm + OFF_XS0;
    float* xs1     = sm + OFF_XS1;
    float* whf     = sm + OFF_WH;        // bf16 [80][168] hi
    float* wlf     = sm + OFF_WL;        // bf16 [80][168] lo
    float* spb_all = sm + OFF_SPB;
    float* w1s     = sm + OFF_W1;
    float* es      = sm + OFF_ES;
    float* psred   = sm + OFF_PS;
    __shared__ int s_flag;

    const int tid  = threadIdx.x;
    const int cta  = blockIdx.x;
    const int nw   = (WORKS - cta + GRIDC - 1) / GRIDC;
    const int lane = tid & 31;
    const int g    = lane >> 2;
    const int tq   = lane & 3;
    const int R0   = (tid >> 5) << 4;    // warp's first row

    // --- prefetch first tile into xs0 ---
    {
        int b = cta >> 5, chunk = cta & 31;
        const char* gb = (const char*)(inputs + ((size_t)b * LL + chunk * TILE_L) * DIN);
        uint32_t sb = smem_u32(xs0);
        for (int c = tid; c < CHUNK16; c += NTH) cp16(sb + c * 16, gb + (size_t)c * 16);
        cp_commit();
    }

    // --- stage W hi/lo bf16 (once): zero pads, then fill k<150, j<75 ---
    for (int idx = tid; idx < 2 * WFLOATS; idx += NTH) whf[idx] = 0.0f;
    __syncthreads();
    for (int idx = tid; idx < 150 * HIDP; idx += NTH) {
        int k = idx / HIDP, j = idx - (idx / HIDP) * HIDP;
        float v = (j < HID) ? W0[(DST + k) * HID + j] : 0.0f;
        __nv_bfloat16 h = __float2bfloat16(v);
        float l = v - __bfloat162float(h);
        ((__nv_bfloat16*)whf)[j * WKS + k] = h;
        ((__nv_bfloat16*)wlf)[j * WKS + k] = __float2bfloat16(l);
    }
    // --- state projections (once) ---
    for (int idx = tid; idx < BB * HIDP; idx += NTH) {
        int b = idx / HIDP, j = idx - (idx / HIDP) * HIDP;
        float acc = 0.0f;
        if (j < HID) {
            acc = b0[j];
            const float* st = state + b * DST;
#pragma unroll 15
            for (int k = 0; k < DST; ++k) acc = fmaf(st[k], W0[k * HID + j], acc);
        }
        spb_all[idx] = acc;
    }
    if (tid < HIDP) w1s[tid] = (tid < HID) ? W1[tid] : 0.0f;

    const float b1v = b1[0];
    const uint32_t whb = smem_u32(whf) + (lane & 7) * WROWB + ((lane >> 3) & 1) * 16;
    const uint32_t wlb = whb + WFLOATS * 4;

    // ---------------- persistent work loop ----------------
    for (int wi = 0; wi < nw; ++wi) {
        const int w     = cta + wi * GRIDC;
        const int b     = w >> 5;
        const int chunk = w & 31;
        const int l0    = chunk * TILE_L;
        float* xsb = (wi & 1) ? xs1 : xs0;

        if (wi + 1 < nw) {
            int w2 = cta + (wi + 1) * GRIDC;
            int b2 = w2 >> 5, ch2 = w2 & 31;
            const char* gb = (const char*)(inputs + ((size_t)b2 * LL + ch2 * TILE_L) * DIN);
            float* dst = ((wi + 1) & 1) ? xs1 : xs0;
            uint32_t sb = smem_u32(dst);
            for (int c = tid; c < CHUNK16; c += NTH) cp16(sb + c * 16, gb + (size_t)c * 16);
            cp_commit();
            cp_wait1();
        } else {
            cp_wait0();
        }
        __syncthreads();     // tile (and wi==0 staging) visible

        // ---- GEMM: D[16 rows x 80 cols] per warp via mma.sync bf16 3x
        float acc[10][4];
#pragma unroll
        for (int n = 0; n < 10; ++n)
#pragma unroll
            for (int c = 0; c < 4; ++c) acc[n][c] = 0.0f;

        const float* row0 = xsb + (size_t)(R0 + g) * DIN;
        const float* row8 = row0 + 8 * DIN;

#pragma unroll
        for (int s = 0; s < 10; ++s) {
            const int kp = s * 16 + tq * 2;
            float2 f00, f10, f01, f11;
            if (s < 9) {
                f00 = *(const float2*)(row0 + kp);
                f10 = *(const float2*)(row8 + kp);
                f01 = *(const float2*)(row0 + kp + 8);
                f11 = *(const float2*)(row8 + kp + 8);
            } else {
                f01 = make_float2(0.f, 0.f); f11 = f01;
                if (tq < 3) {      // k pairs 144/146/148 valid; tq==3 -> k=150
                    f00 = *(const float2*)(row0 + kp);
                    f10 = *(const float2*)(row8 + kp);
                } else { f00 = f01; f10 = f01; }
            }
            uint32_t ah0 = bfpack(f00), ah1 = bfpack(f10);
            uint32_t ah2 = bfpack(f01), ah3 = bfpack(f11);
            uint32_t al0 = bfres(f00, ah0), al1 = bfres(f10, ah1);
            uint32_t al2 = bfres(f01, ah2), al3 = bfres(f11, ah3);
#pragma unroll
            for (int n = 0; n < 10; ++n) {
                uint32_t bh0, bh1, bl0, bl1;
                LDSM_X2(bh0, bh1, whb + n * 2688 + s * 32);
                LDSM_X2(bl0, bl1, wlb + n * 2688 + s * 32);
                MMA_BF16(acc[n], ah0, ah1, ah2, ah3, bh0, bh1);
                MMA_BF16(acc[n], ah0, ah1, ah2, ah3, bl0, bl1);
                MMA_BF16(acc[n], al0, al1, al2, al3, bh0, bh1);
            }
        }

        // ---- epilogue: tanh + dot(W1), quad reduce, mask + exp
        {
            const float* spb = spb_all + b * HIDP;
            float sA = 0.0f, sB = 0.0f;
#pragma unroll
            for (int n = 0; n < 10; ++n) {
                int c = n * 8 + tq * 2;
                float wv0 = w1s[c], wv1 = w1s[c + 1];
                float p0 = spb[c],  p1 = spb[c + 1];
                sA = fmaf(tanh_approx(acc[n][0] + p0), wv0, sA);
                sA = fmaf(tanh_approx(acc[n][1] + p1), wv1, sA);
                sB = fmaf(tanh_approx(acc[n][2] + p0), wv0, sB);
                sB = fmaf(tanh_approx(acc[n][3] + p1), wv1, sB);
            }
            sA += __shfl_xor_sync(0xffffffffu, sA, 1);
            sA += __shfl_xor_sync(0xffffffffu, sA, 2);
            sB += __shfl_xor_sync(0xffffffffu, sB, 1);
            sB += __shfl_xor_sync(0xffffffffu, sB, 2);
            if (tq == 0) {
                int r = R0 + g;
                size_t idx = (size_t)b * LL + l0 + r;
                float sv = sA + b1v;
                if (cmask[idx] == 0) sv -= 1e30f;
                s1_out[idx] = sv;
                es[r] = __expf(sv);
                int r2 = r + 8;
                size_t idx2 = (size_t)b * LL + l0 + r2;
                float sv2 = sB + b1v;
                if (cmask[idx2] == 0) sv2 -= 1e30f;
                s1_out[idx2] = sv2;
                es[r2] = __expf(sv2);
            }
        }
        __syncthreads();

        // ---- fused weighted partial sums from resident fp32 tile
        if (tid < DIN) {
            const float* xcol = xsb + tid;
            float p = 0.0f;
#pragma unroll 8
            for (int r = 0; r < TILE_L; ++r)
                p = fmaf(es[r], xcol[(size_t)r * DIN], p);
            g_part[b][chunk][tid] = p;
        }
        if (tid < TILE_L) {
            float v = es[tid];
            v += __shfl_xor_sync(0xffffffffu, v, 16);
            v += __shfl_xor_sync(0xffffffffu, v, 8);
            v += __shfl_xor_sync(0xffffffffu, v, 4);
            v += __shfl_xor_sync(0xffffffffu, v, 2);
            v += __shfl_xor_sync(0xffffffffu, v, 1);
            if ((tid & 31) == 0) psred[tid >> 5] = v;
        }
        __syncthreads();
        if (tid == 0) {
            g_psum[b][chunk] = (psred[0] + psred[1]) + (psred[2] + psred[3]);
            __threadfence();
            int old = atomicAdd(&g_done_b[b], 1);
            s_flag = (old == NCHUNK - 1);
        }
        __syncthreads();
        if (s_flag) {
            __threadfence();
            if (tid < DIN) {
                float tot = 0.0f;
#pragma unroll
                for (int c = 0; c < NCHUNK; ++c) tot += g_psum[b][c];
                float p = 0.0f;
#pragma unroll
                for (int c = 0; c < NCHUNK; ++c) p += g_part[b][c][tid];
                res[b * DIN + tid] = p / tot;
            }
            if (tid == 0) g_done_b[b] = 0;
        }
        __syncthreads();
    }
}

// ---------------------------------------------------------------------------
extern "C" void kernel_launch(void* const* d_in, const int* in_sizes, int n_in,
                              void* d_out, int out_size) {
    const float* inputs = (const float*)d_in[0];
    const float* state  = (const float*)d_in[1];
    const int*   cmask  = (const int*)d_in[2];   // bool transported as int32
    const float* W0     = (const float*)d_in[3];
    const float* b0     = (const float*)d_in[4];
    const float* W1     = (const float*)d_in[5];
    const float* b1     = (const float*)d_in[6];

    float* out = (float*)d_out;
    float* res = out;                 // [B][1][DIN]
    float* s1  = out + BB * DIN;      // [B][L]

    const int smem = SMEM_FLOATS * (int)sizeof(float);
    cudaFuncSetAttribute(k_fused, cudaFuncAttributeMaxDynamicSharedMemorySize, smem);
    k_fused<<<GRIDC, NTH, smem>>>(inputs, state, cmask, W0, b0, W1, b1, res, s1);
}